// round 16
// baseline (speedup 1.0000x reference)
#include <cuda_runtime.h>
#include <cuda_bf16.h>
#include <cuda_fp16.h>
#include <cstdint>

#define N_NODES 50000
#define N_EDGES 800000
#define IN_F 128
#define OUT_F 128
#define NEIG 64
#define HDIM 128
#define XT_COLS 384      // [X1|X2|X3]; X0=feature, hs folded into GEMM K-cols
#define N_CHUNKS 9       // K chunks of 64 (total K = 576)
#define N_TILES 391      // ceil(50000/128)
#define CHEB_BLOCKS 6250 // 6250 blocks x 8 warps = 50000 warps exactly

// ---------------- scratch (device globals; no allocation allowed) --------------
__device__ float g_Xt[(size_t)N_NODES * XT_COLS];
__device__ __half g_Xh[3][(size_t)N_NODES * IN_F];   // fp16 gather copies: X0,X1,X2
__device__ float g_dsqrt[N_NODES];
__device__ int   g_deg[N_NODES];
__device__ int   g_rowstart[N_NODES + 1];
__device__ int   g_cursor[N_NODES];
__device__ int   g_csrsrc[N_EDGES];
__device__ int   g_blocksum[256];
__device__ int   g_blockoff[256];
__device__ int   g_scan_count;
__device__ volatile int g_scan_done;
__device__ float g_ef[NEIG];
__device__ float g_hs_small[NEIG * OUT_F];
__device__ float g_colsum[OUT_F];
__device__ float g_colsq[OUT_F];
__device__ int   g_is64;
// packed bf16 B' tiles: 9 chunks x (hi 16KB + lo 16KB), SW128-swizzled [128 n][64 k]
__device__ __align__(128) uint8_t g_Bpack[(size_t)N_CHUNKS * 32768];
// packed bf16 A tiles: [tile 391][chunk 9][hi 16KB + lo 16KB]
__device__ __align__(128) uint8_t g_Apack[(size_t)N_TILES * N_CHUNKS * 32768];

// ---------------- helpers --------------------------------------------------------
__device__ __forceinline__ uint32_t smem_u32(const void* p) {
    uint32_t a;
    asm("{ .reg .u64 t; cvta.to.shared.u64 t, %1; cvt.u32.u64 %0, t; }" : "=r"(a) : "l"(p));
    return a;
}
#define SW128(o) ((o) ^ (((o) >> 3) & 0x70))
#define CPASYNC16(dst, src) \
    asm volatile("cp.async.cg.shared.global [%0], [%1], 16;" :: "r"(dst), "l"(src))
#define CPASYNC_COMMIT() asm volatile("cp.async.commit_group;" ::: "memory")
#define CPASYNC_WAIT0()  asm volatile("cp.async.wait_group 0;" ::: "memory")

__device__ __forceinline__ void ldsm4(uint32_t* r, uint32_t addr) {
    asm volatile("ldmatrix.sync.aligned.m8n8.x4.shared.b16 {%0,%1,%2,%3}, [%4];"
                 : "=r"(r[0]), "=r"(r[1]), "=r"(r[2]), "=r"(r[3]) : "r"(addr));
}
__device__ __forceinline__ void ldsm2(uint32_t* r, uint32_t addr) {
    asm volatile("ldmatrix.sync.aligned.m8n8.x2.shared.b16 {%0,%1}, [%2];"
                 : "=r"(r[0]), "=r"(r[1]) : "r"(addr));
}
__device__ __forceinline__ void mma_bf16(float* c, const uint32_t* a, const uint32_t* b) {
    asm volatile("mma.sync.aligned.m16n8k16.row.col.f32.bf16.bf16.f32 "
                 "{%0,%1,%2,%3}, {%4,%5,%6,%7}, {%8,%9}, {%0,%1,%2,%3};"
                 : "+f"(c[0]), "+f"(c[1]), "+f"(c[2]), "+f"(c[3])
                 : "r"(a[0]), "r"(a[1]), "r"(a[2]), "r"(a[3]), "r"(b[0]), "r"(b[1]));
}
__device__ __forceinline__ void split2(float v0, float v1, uint32_t& hi, uint32_t& lo) {
    __nv_bfloat162 hp = __floats2bfloat162_rn(v0, v1);
    float h0 = __bfloat162float(__low2bfloat16(hp));
    float h1 = __bfloat162float(__high2bfloat16(hp));
    __nv_bfloat162 lp = __floats2bfloat162_rn(v0 - h0, v1 - h1);
    hi = *reinterpret_cast<uint32_t*>(&hp);
    lo = *reinterpret_cast<uint32_t*>(&lp);
}
__device__ __forceinline__ int edge_at(const void* p, int e) {
    return g_is64 ? (int)((const long long*)p)[e] : ((const int*)p)[e];
}
// gather 4 halfs (8 bytes) -> float4
__device__ __forceinline__ float4 gather_h4(const __half* base, int node, int lane) {
    uint2 raw = *(const uint2*)(base + (size_t)node * IN_F + lane * 4);
    __half2 h0 = *reinterpret_cast<__half2*>(&raw.x);
    __half2 h1 = *reinterpret_cast<__half2*>(&raw.y);
    float2 f0 = __half22float2(h0), f1 = __half22float2(h1);
    return make_float4(f0.x, f0.y, f1.x, f1.y);
}
__device__ __forceinline__ void store_splitB(uint32_t base_off, uint32_t sw, float v0, float v1) {
    uint32_t hi, lo;
    split2(v0, v1, hi, lo);
    *(uint32_t*)(g_Bpack + base_off + sw)         = hi;
    *(uint32_t*)(g_Bpack + base_off + 16384 + sw) = lo;
}

// ---------------- init (+ dtype detect fused) -----------------------------------
__global__ void k_init(const void* __restrict__ dst) {
    int i = blockIdx.x * blockDim.x + threadIdx.x;
    if (i == 0) {
        const long long* p = (const long long*)dst;
        int ok = 1;
        for (int q = 0; q < 64; q++) {
            long long v = p[q];
            if (v < 0 || v >= N_NODES) { ok = 0; break; }
        }
        g_is64 = ok;
        g_scan_count = 0;
        g_scan_done = 0;
    }
    if (i < N_NODES) g_deg[i] = 0;
    if (i < NEIG * OUT_F) g_hs_small[i] = 0.f;
    if (i < OUT_F) { g_colsum[i] = 0.f; g_colsq[i] = 0.f; }
}

// ---------------- fused: count (4 chains) | prepA | prepB chunks 0-7 -------------
#define CP_COUNT 782                         // ceil(800000/4/256)
#define CP_PREPA 18750                       // 50000*96/256
#define CP_C2 (CP_COUNT + CP_PREPA)          // 19532
#define CP_TOTAL (CP_C2 + 128)               // + prepB chunks 0-7
__global__ __launch_bounds__(256) void k_cntprep(const void* __restrict__ e_dst,
                                                 const float* __restrict__ feature,
                                                 const float* __restrict__ evecs,
                                                 const float* __restrict__ lin_w) {
    int b = blockIdx.x, t = threadIdx.x;
    if (b < CP_COUNT) {
        int e = (b * 256 + t) * 4;
        if (e >= N_EDGES) return;
        int d0 = edge_at(e_dst, e);
        int d1 = edge_at(e_dst, e + 1);
        int d2 = edge_at(e_dst, e + 2);
        int d3 = edge_at(e_dst, e + 3);
        atomicAdd(&g_deg[d0], 1);
        atomicAdd(&g_deg[d1], 1);
        atomicAdd(&g_deg[d2], 1);
        atomicAdd(&g_deg[d3], 1);
    } else if (b < CP_C2) {
        int idx = (b - CP_COUNT) * 256 + t;   // float2 slots: 50000*96 exactly
        int n = idx / 96, s = idx - n * 96;
        float2 v; int chunk, kp;
        if (s < 64) {
            v = *(const float2*)(feature + (size_t)n * IN_F + s * 2);
            chunk = s >> 5;
            kp = s & 31;
            __half2 h = __floats2half2_rn(v.x, v.y);
            *(__half2*)(g_Xh[0] + (size_t)n * IN_F + s * 2) = h;
        } else {
            int e = s - 64;
            v = *(const float2*)(evecs + (size_t)n * NEIG + e * 2);
            chunk = 8;
            kp = e;
        }
        uint32_t hi, lo;
        split2(v.x, v.y, hi, lo);
        uint8_t* base = g_Apack + ((size_t)(n >> 7) * N_CHUNKS + chunk) * 32768;
        uint32_t sw = SW128((uint32_t)((n & 127) * 128 + kp * 4));
        *(uint32_t*)(base + sw)         = hi;
        *(uint32_t*)(base + 16384 + sw) = lo;
    } else {
        // prepB chunks 0-7: weight transpose + bf16 split (independent of CSR)
        int idx = (b - CP_C2) * 256 + t;      // < 32768
        int chunk = idx >> 12;
        int rem = idx & 4095;
        int n = rem >> 5, kp = rem & 31;
        int k = chunk * 64 + kp * 2;
        float v0 = lin_w[(size_t)k * OUT_F + n];
        float v1 = lin_w[(size_t)(k + 1) * OUT_F + n];
        store_splitB((uint32_t)chunk * 32768u, SW128((uint32_t)(n * 128 + kp * 4)), v0, v1);
    }
}

// ---------------- single-kernel scan: local scan + last-block + spin-join --------
__global__ void k_scan() {
    __shared__ int sm[256];
    __shared__ int amLast;
    int t = threadIdx.x, i = blockIdx.x * 256 + t;
    int v = (i < N_NODES) ? g_deg[i] : 0;
    if (i < N_NODES) g_dsqrt[i] = rsqrtf(fmaxf((float)v, 1.f));
    sm[t] = v;
    __syncthreads();
    for (int off = 1; off < 256; off <<= 1) {
        int tmp = (t >= off) ? sm[t - off] : 0;
        __syncthreads();
        sm[t] += tmp;
        __syncthreads();
    }
    int excl = sm[t] - v;                         // block-local exclusive prefix
    if (t == 255) g_blocksum[blockIdx.x] = sm[255];
    __threadfence();
    if (t == 0) {
        int c = atomicAdd(&g_scan_count, 1);
        amLast = (c == (int)gridDim.x - 1);
    }
    __syncthreads();
    if (amLast) {
        int nb = (int)gridDim.x;                  // 196
        int v2 = (t < nb) ? g_blocksum[t] : 0;
        sm[t] = v2;
        __syncthreads();
        for (int off = 1; off < 256; off <<= 1) {
            int tmp = (t >= off) ? sm[t - off] : 0;
            __syncthreads();
            sm[t] += tmp;
            __syncthreads();
        }
        g_blockoff[t] = sm[t] - v2;
        if (t == 255) g_rowstart[N_NODES] = sm[255];
        __threadfence();
        __syncthreads();
        if (t == 0) g_scan_done = 1;
    }
    // spin-join: all 196 blocks are co-resident (148 SMs), so this cannot deadlock
    if (t == 0) {
        while (g_scan_done == 0) { }
        amLast = 1;                               // reuse as "released" marker
    }
    __syncthreads();
    __threadfence();                              // acquire side for g_blockoff
    if (i < N_NODES) {
        int r = excl + *(volatile int*)&g_blockoff[blockIdx.x];
        g_rowstart[i] = r;
        g_cursor[i] = r;
    }
}

// ---------------- place: 4 independent edge chains per thread --------------------
__global__ void k_place(const void* __restrict__ src, const void* __restrict__ dst) {
    int e = (blockIdx.x * blockDim.x + threadIdx.x) * 4;
    if (e >= N_EDGES) return;
    int d0 = edge_at(dst, e);
    int d1 = edge_at(dst, e + 1);
    int d2 = edge_at(dst, e + 2);
    int d3 = edge_at(dst, e + 3);
    int s0 = edge_at(src, e);
    int s1 = edge_at(src, e + 1);
    int s2 = edge_at(src, e + 2);
    int s3 = edge_at(src, e + 3);
    int p0 = atomicAdd(&g_cursor[d0], 1);
    int p1 = atomicAdd(&g_cursor[d1], 1);
    int p2 = atomicAdd(&g_cursor[d2], 1);
    int p3 = atomicAdd(&g_cursor[d3], 1);
    g_csrsrc[p0] = s0;
    g_csrsrc[p1] = s1;
    g_csrsrc[p2] = s2;
    g_csrsrc[p3] = s3;
}

// ---------------- fused: hsacc | eigen MLP ---------------------------------------
#define EH_HSACC 196
__global__ __launch_bounds__(256) void k_eighs(
    const float* __restrict__ evecs, const float* __restrict__ feat,
    const float* __restrict__ evals,
    const float* __restrict__ ew0, const float* __restrict__ eb0,
    const float* __restrict__ ew1, const float* __restrict__ eb1,
    const float* __restrict__ ew2, const float* __restrict__ eb2) {
    int b = blockIdx.x, t = threadIdx.x;
    if (b < EH_HSACC) {
        // ---- hsacc: hs_small = evecs^T @ feature ----
        __shared__ float sev[8][64];
        int f = t & 127;
        int ebase = (t >> 7) * 32;
        float acc[32];
        #pragma unroll
        for (int u = 0; u < 32; u++) acc[u] = 0.f;
        int r0 = b * 256;
        for (int rt = 0; rt < 256; rt += 8) {
            #pragma unroll
            for (int q = 0; q < 2; q++) {
                int idx = q * 256 + t;
                int rr = idx >> 6, ee = idx & 63;
                int grow = r0 + rt + rr;
                sev[rr][ee] = (grow < N_NODES) ? evecs[(size_t)grow * NEIG + ee] : 0.f;
            }
            __syncthreads();
            #pragma unroll
            for (int rr = 0; rr < 8; rr++) {
                int grow = r0 + rt + rr;
                float ftv = (grow < N_NODES) ? feat[(size_t)grow * IN_F + f] : 0.f;
                #pragma unroll
                for (int u4 = 0; u4 < 8; u4++) {
                    float4 ev = *(const float4*)&sev[rr][ebase + u4 * 4];
                    acc[u4*4+0] = fmaf(ev.x, ftv, acc[u4*4+0]);
                    acc[u4*4+1] = fmaf(ev.y, ftv, acc[u4*4+1]);
                    acc[u4*4+2] = fmaf(ev.z, ftv, acc[u4*4+2]);
                    acc[u4*4+3] = fmaf(ev.w, ftv, acc[u4*4+3]);
                }
            }
            __syncthreads();
        }
        #pragma unroll
        for (int u = 0; u < 32; u++)
            atomicAdd(&g_hs_small[(ebase + u) * OUT_F + f], acc[u]);
    } else {
        // ---- eigen MLP -> g_ef[i] (threads 0..127 active) ----
        __shared__ float z0s[HDIM];
        __shared__ float sp[HDIM];
        int i = b - EH_HSACC;
        if (t < HDIM) z0s[t] = fmaxf(fmaf(evals[i], ew0[t], eb0[t]), 0.f);
        __syncthreads();
        if (t < HDIM) {
            float sA = eb1[t], sB = 0.f;
            #pragma unroll 8
            for (int k = 0; k < HDIM; k += 2) {
                sA = fmaf(z0s[k],     ew1[k * HDIM + t],       sA);
                sB = fmaf(z0s[k + 1], ew1[(k + 1) * HDIM + t], sB);
            }
            sp[t] = fmaxf(sA + sB, 0.f) * ew2[t];
        }
        __syncthreads();
        for (int off = 64; off > 0; off >>= 1) {
            if (t < off) sp[t] += sp[t + off];
            __syncthreads();
        }
        if (t == 0) g_ef[i] = sp[0] + eb2[0];
    }
}

// ---------------- Chebyshev step: fp16 gather (4-edge unroll), fp32 self-terms ---
// blocks >= CHEB_BLOCKS (present only on the X3 launch) run prepB chunk 8.
__global__ void k_cheb(const float* __restrict__ lambda_max,
                       const float* __restrict__ feature,
                       const float* __restrict__ lin_w,
                       int prevh,                 // fp16 gather source index
                       int prevsel, int prev2sel, // fp32 self-term sources (-1 = feature)
                       int outcol, int first,
                       int chunk_base, int writeXt, int outh) {
    if (blockIdx.x >= CHEB_BLOCKS) {
        // ---- prepB chunk 8: B'[n][e] = ef[e] * (hs_small[e] . lin_w[512+..][n]) ----
        int idx = (blockIdx.x - CHEB_BLOCKS) * 256 + threadIdx.x;   // < 4096
        int n = idx >> 5, ep = idx & 31;
        int e0 = ep * 2, e1 = e0 + 1;
        float s0 = 0.f, s1 = 0.f;
        #pragma unroll 4
        for (int f = 0; f < 128; f++) {
            float w = lin_w[(size_t)(512 + f) * OUT_F + n];
            s0 = fmaf(g_hs_small[e0 * OUT_F + f], w, s0);
            s1 = fmaf(g_hs_small[e1 * OUT_F + f], w, s1);
        }
        s0 *= g_ef[e0];
        s1 *= g_ef[e1];
        store_splitB(8u * 32768u, SW128((uint32_t)(n * 128 + ep * 4)), s0, s1);
        return;
    }
    int gwarp = (blockIdx.x * blockDim.x + threadIdx.x) >> 5;
    if (gwarp >= N_NODES) return;
    int lane = threadIdx.x & 31;
    const __half* hx = g_Xh[prevh];
    const float* prev;  size_t ps;
    if (prevsel < 0) { prev = feature; ps = IN_F; }
    else             { prev = g_Xt + prevsel; ps = XT_COLS; }
    int beg = g_rowstart[gwarp], end = g_rowstart[gwarp + 1];
    float4 acc = {0.f, 0.f, 0.f, 0.f};
    int j = beg;
    for (; j + 3 < end; j += 4) {
        int s0 = g_csrsrc[j],     s1 = g_csrsrc[j + 1];
        int s2 = g_csrsrc[j + 2], s3 = g_csrsrc[j + 3];
        float d0 = g_dsqrt[s0], d1 = g_dsqrt[s1];
        float d2 = g_dsqrt[s2], d3 = g_dsqrt[s3];
        float4 v0 = gather_h4(hx, s0, lane);
        float4 v1 = gather_h4(hx, s1, lane);
        float4 v2 = gather_h4(hx, s2, lane);
        float4 v3 = gather_h4(hx, s3, lane);
        acc.x = fmaf(v0.x, d0, acc.x); acc.y = fmaf(v0.y, d0, acc.y);
        acc.z = fmaf(v0.z, d0, acc.z); acc.w = fmaf(v0.w, d0, acc.w);
        acc.x = fmaf(v1.x, d1, acc.x); acc.y = fmaf(v1.y, d1, acc.y);
        acc.z = fmaf(v1.z, d1, acc.z); acc.w = fmaf(v1.w, d1, acc.w);
        acc.x = fmaf(v2.x, d2, acc.x); acc.y = fmaf(v2.y, d2, acc.y);
        acc.z = fmaf(v2.z, d2, acc.z); acc.w = fmaf(v2.w, d2, acc.w);
        acc.x = fmaf(v3.x, d3, acc.x); acc.y = fmaf(v3.y, d3, acc.y);
        acc.z = fmaf(v3.z, d3, acc.z); acc.w = fmaf(v3.w, d3, acc.w);
    }
    for (; j < end; j++) {
        int s0 = g_csrsrc[j];
        float d0 = g_dsqrt[s0];
        float4 v0 = gather_h4(hx, s0, lane);
        acc.x = fmaf(v0.x, d0, acc.x); acc.y = fmaf(v0.y, d0, acc.y);
        acc.z = fmaf(v0.z, d0, acc.z); acc.w = fmaf(v0.w, d0, acc.w);
    }
    float rn = 2.f / lambda_max[0];
    float dn = g_dsqrt[gwarp];
    float alpha = (first ? -rn : -2.f * rn) * dn;
    float beta  = first ? (rn - 1.f) : 2.f * (rn - 1.f);
    float4 xp = *(const float4*)(prev + (size_t)gwarp * ps + lane * 4);
    float4 r;
    r.x = alpha * acc.x + beta * xp.x;
    r.y = alpha * acc.y + beta * xp.y;
    r.z = alpha * acc.z + beta * xp.z;
    r.w = alpha * acc.w + beta * xp.w;
    if (!first) {
        const float* p2; size_t p2s;
        if (prev2sel < 0) { p2 = feature; p2s = IN_F; }
        else              { p2 = g_Xt + prev2sel; p2s = XT_COLS; }
        float4 xpp = *(const float4*)(p2 + (size_t)gwarp * p2s + lane * 4);
        r.x -= xpp.x; r.y -= xpp.y; r.z -= xpp.z; r.w -= xpp.w;
    }
    if (writeXt)
        *(float4*)(g_Xt + (size_t)gwarp * XT_COLS + outcol + lane * 4) = r;
    if (outh >= 0) {
        __half2 ha = __floats2half2_rn(r.x, r.y);
        __half2 hb = __floats2half2_rn(r.z, r.w);
        uint2 packed;
        packed.x = *reinterpret_cast<uint32_t*>(&ha);
        packed.y = *reinterpret_cast<uint32_t*>(&hb);
        *(uint2*)(g_Xh[outh] + (size_t)gwarp * IN_F + lane * 4) = packed;
    }

    // --- emit bf16 hi/lo into pre-swizzled A panel ---
    int tile = gwarp >> 7, rowr = gwarp & 127;
    int chunk = chunk_base + ((lane & 16) >> 4);
    uint8_t* base = g_Apack + ((size_t)tile * N_CHUNKS + chunk) * 32768;
    uint32_t sw = SW128((uint32_t)(rowr * 128 + (lane & 15) * 8));
    uint32_t hi0, lo0, hi1, lo1;
    split2(r.x, r.y, hi0, lo0);
    split2(r.z, r.w, hi1, lo1);
    *(uint32_t*)(base + sw)             = hi0;
    *(uint32_t*)(base + sw + 4)         = hi1;
    *(uint32_t*)(base + 16384 + sw)     = lo0;
    *(uint32_t*)(base + 16384 + sw + 4) = lo1;
}

// ---------------- HMMA GEMM: cp.async tile copies + mma, fused BN stats ----------
#define A_HI 0
#define A_LO 16384
#define B_HI 32768
#define B_LO 49152
#define SMEM_GEMM 65536
__global__ __launch_bounds__(256, 2) void k_gemm_mma(const float* __restrict__ bias,
                                                     float* __restrict__ C) {
    extern __shared__ __align__(16) char smem[];
    uint32_t sb = smem_u32(smem);
    int tid = threadIdx.x, wid = tid >> 5, lane = tid & 31;
    int rowBase = blockIdx.x * 128;
    int rowW = (wid & 3) * 32;
    int colW = (wid >> 2) * 64;

    float c[2][8][4];
    #pragma unroll
    for (int mt = 0; mt < 2; mt++)
        #pragma unroll
        for (int nt = 0; nt < 8; nt++)
            #pragma unroll
            for (int q = 0; q < 4; q++) c[mt][nt][q] = 0.f;

    uint32_t a_row = (uint32_t)(lane & 15);
    uint32_t a_koff = (lane & 16) ? 16u : 0u;
    uint32_t b_row = (uint32_t)(lane & 7);
    uint32_t b_koff = (lane & 8) ? 16u : 0u;

    for (int ch = 0; ch < N_CHUNKS; ch++) {
        __syncthreads();
        const char* asrc = (const char*)(g_Apack + ((size_t)blockIdx.x * N_CHUNKS + ch) * 32768);
        const char* bsrc = (const char*)(g_Bpack + (size_t)ch * 32768);
        #pragma unroll
        for (int q = 0; q < 8; q++)
            CPASYNC16(sb + (uint32_t)(q * 4096 + tid * 16), asrc + q * 4096 + tid * 16);
        #pragma unroll
        for (int q = 0; q < 8; q++)
            CPASYNC16(sb + (uint32_t)(32768 + q * 4096 + tid * 16), bsrc + q * 4096 + tid * 16);
        CPASYNC_COMMIT();
        CPASYNC_WAIT0();
        __syncthreads();

        #pragma unroll
        for (int ks = 0; ks < 4; ks++) {
            uint32_t kb = (uint32_t)ks * 32;
            uint32_t ah[2][4], al[2][4];
            #pragma unroll
            for (int mt = 0; mt < 2; mt++) {
                uint32_t off = SW128((uint32_t)(rowW + mt * 16 + a_row) * 128 + kb + a_koff);
                ldsm4(ah[mt], sb + A_HI + off);
                ldsm4(al[mt], sb + A_LO + off);
            }
            #pragma unroll
            for (int nt = 0; nt < 8; nt++) {
                uint32_t boff = SW128((uint32_t)(colW + nt * 8 + b_row) * 128 + kb + b_koff);
                uint32_t bh[2], bl[2];
                ldsm2(bh, sb + B_HI + boff);
                ldsm2(bl, sb + B_LO + boff);
                #pragma unroll
                for (int mt = 0; mt < 2; mt++) {
                    mma_bf16(c[mt][nt], ah[mt], bh);
                    mma_bf16(c[mt][nt], ah[mt], bl);
                    mma_bf16(c[mt][nt], al[mt], bh);
                }
            }
        }
    }

    // --- epilogue: bias add, store, fused BN column sums ---
    int lane4 = lane & 3, lanerow = lane >> 2;
    float ps[8][2], pq[8][2];
    #pragma unroll
    for (int nt = 0; nt < 8; nt++) { ps[nt][0] = ps[nt][1] = pq[nt][0] = pq[nt][1] = 0.f; }

    #pragma unroll
    for (int mt = 0; mt < 2; mt++) {
        #pragma unroll
        for (int half = 0; half < 2; half++) {
            int grow = rowBase + rowW + mt * 16 + lanerow + half * 8;
            bool valid = grow < N_NODES;
            #pragma unroll
            for (int nt = 0; nt < 8; nt++) {
                int col = colW + nt * 8 + lane4 * 2;
                float v0 = 0.f, v1 = 0.f;
                if (valid) {
                    v0 = c[mt][nt][half * 2 + 0] + __ldg(bias + col);
                    v1 = c[mt][nt][half * 2 + 1] + __ldg(bias + col + 1);
                    float2 w = {v0, v1};
                    *(float2*)(C + (size_t)grow * OUT_F + col) = w;
                }
                ps[nt][0] += v0; ps[nt][1] += v1;
                pq[nt][0] += v0 * v0; pq[nt][1] += v1 * v1;
            }
        }
    }
    #pragma unroll
    for (int nt = 0; nt < 8; nt++) {
        #pragma unroll
        for (int j = 0; j < 2; j++) {
            float s = ps[nt][j], q = pq[nt][j];
            #pragma unroll
            for (int m = 4; m < 32; m <<= 1) {
                s += __shfl_xor_sync(0xffffffffu, s, m);
                q += __shfl_xor_sync(0xffffffffu, q, m);
            }
            if (lanerow == 0) {
                int col = colW + nt * 8 + lane4 * 2 + j;
                atomicAdd(&g_colsum[col], s);
                atomicAdd(&g_colsq[col], q);
            }
        }
    }
}

// ---------------- batch-norm normalize -------------------------------------------
__global__ void k_bnnorm(float* __restrict__ out, const float* __restrict__ gamma,
                         const float* __restrict__ beta) {
    int idx = blockIdx.x * blockDim.x + threadIdx.x;   // float4 index
    if (idx >= N_NODES * 32) return;
    int c4 = idx & 31;
    float4 v = ((float4*)out)[idx];
    float invN = 1.f / (float)N_NODES;
    float r[4];
    float* pv = &v.x;
    #pragma unroll
    for (int u = 0; u < 4; u++) {
        int c = c4 * 4 + u;
        float mu = g_colsum[c] * invN;
        float var = g_colsq[c] * invN - mu * mu;
        float rs = rsqrtf(var + 1e-5f);
        r[u] = fmaxf((pv[u] - mu) * rs * gamma[c] + beta[c], 0.f);
    }
    v.x = r[0]; v.y = r[1]; v.z = r[2]; v.w = r[3];
    ((float4*)out)[idx] = v;
}

// ---------------- launch ----------------------------------------------------------
extern "C" void kernel_launch(void* const* d_in, const int* in_sizes, int n_in,
                              void* d_out, int out_size) {
    const float* feature    = (const float*)d_in[0];
    const float* lin_w      = (const float*)d_in[1];
    const float* lin_b      = (const float*)d_in[2];
    const float* ew0        = (const float*)d_in[3];
    const float* eb0        = (const float*)d_in[4];
    const float* ew1        = (const float*)d_in[5];
    const float* eb1        = (const float*)d_in[6];
    const float* ew2        = (const float*)d_in[7];
    const float* eb2        = (const float*)d_in[8];
    const float* bn_gamma   = (const float*)d_in[9];
    const float* bn_beta    = (const float*)d_in[10];
    const float* lambda_max = (const float*)d_in[11];
    const float* evecs      = (const float*)d_in[12];
    const float* evals      = (const float*)d_in[13];
    const void*  e_src      = (const void*)d_in[14];
    const void*  e_dst      = (const void*)d_in[15];
    float* out = (float*)d_out;

    const int TB = 256;
    int gN    = (N_NODES + TB - 1) / TB;             // 196
    int gE4   = (N_EDGES / 4 + TB - 1) / TB;         // 782
    int gF4   = (N_NODES * 32 + TB - 1) / TB;        // 6250

    cudaFuncSetAttribute(k_gemm_mma, cudaFuncAttributeMaxDynamicSharedMemorySize, SMEM_GEMM);

    k_init<<<gN, TB>>>(e_dst);
    k_cntprep<<<CP_TOTAL, TB>>>(e_dst, feature, evecs, lin_w);  // count | prepA | prepB0-7
    k_scan<<<gN, TB>>>();                                       // scan + offset + cursor
    k_place<<<gE4, TB>>>(e_src, e_dst);
    k_eighs<<<EH_HSACC + NEIG, TB>>>(evecs, feature, evals,
                                     ew0, eb0, ew1, eb1, ew2, eb2);  // hsacc | eig

    // cheb: fp16 gather source, fp32 self-terms, fp16 output copy for next level
    k_cheb<<<CHEB_BLOCKS, TB>>>(lambda_max, feature, lin_w, 0,  -1,  -1,   0, 1, 2, 1, 1);  // X1
    k_cheb<<<CHEB_BLOCKS, TB>>>(lambda_max, feature, lin_w, 1,   0,  -1, 128, 0, 4, 1, 2);  // X2
    k_cheb<<<CHEB_BLOCKS + 16, TB>>>(lambda_max, feature, lin_w, 2, 128, 0, 256, 0, 6, 0, -1); // X3 | prepB8

    k_gemm_mma<<<N_TILES, TB, SMEM_GEMM>>>(lin_b, out);

    k_bnnorm<<<gF4, TB>>>(out, bn_gamma, bn_beta);
}

// round 17
// speedup vs baseline: 1.1170x; 1.1170x over previous
#include <cuda_runtime.h>
#include <cuda_bf16.h>
#include <cuda_fp16.h>
#include <cstdint>

#define N_NODES 50000
#define N_EDGES 800000
#define IN_F 128
#define OUT_F 128
#define NEIG 64
#define HDIM 128
#define XT_COLS 384      // [X1|X2|X3]; X0=feature, hs folded into GEMM K-cols
#define N_CHUNKS 9       // K chunks of 64 (total K = 576)
#define N_TILES 391      // ceil(50000/128)

// ---------------- scratch (device globals; no allocation allowed) --------------
__device__ float g_Xt[(size_t)N_NODES * XT_COLS];
__device__ __half g_Xh[3][(size_t)N_NODES * IN_F];   // fp16 gather copies: X0,X1,X2
__device__ float g_dsqrt[N_NODES];
__device__ int   g_deg[N_NODES];
__device__ int   g_rowstart[N_NODES + 1];
__device__ int   g_cursor[N_NODES];
__device__ int   g_csrsrc[N_EDGES];
__device__ int   g_blocksum[256];
__device__ int   g_blockoff[256];
__device__ int   g_scan_count;
__device__ float g_ef[NEIG];
__device__ float g_hs_small[NEIG * OUT_F];
__device__ float g_colsum[OUT_F];
__device__ float g_colsq[OUT_F];
__device__ int   g_is64;
// packed bf16 B' tiles: 9 chunks x (hi 16KB + lo 16KB), SW128-swizzled [128 n][64 k]
__device__ __align__(128) uint8_t g_Bpack[(size_t)N_CHUNKS * 32768];
// packed bf16 A tiles: [tile 391][chunk 9][hi 16KB + lo 16KB]
__device__ __align__(128) uint8_t g_Apack[(size_t)N_TILES * N_CHUNKS * 32768];

// ---------------- helpers --------------------------------------------------------
__device__ __forceinline__ uint32_t smem_u32(const void* p) {
    uint32_t a;
    asm("{ .reg .u64 t; cvta.to.shared.u64 t, %1; cvt.u32.u64 %0, t; }" : "=r"(a) : "l"(p));
    return a;
}
#define SW128(o) ((o) ^ (((o) >> 3) & 0x70))
#define CPASYNC16(dst, src) \
    asm volatile("cp.async.cg.shared.global [%0], [%1], 16;" :: "r"(dst), "l"(src))
#define CPASYNC_COMMIT() asm volatile("cp.async.commit_group;" ::: "memory")
#define CPASYNC_WAIT0()  asm volatile("cp.async.wait_group 0;" ::: "memory")

__device__ __forceinline__ void ldsm4(uint32_t* r, uint32_t addr) {
    asm volatile("ldmatrix.sync.aligned.m8n8.x4.shared.b16 {%0,%1,%2,%3}, [%4];"
                 : "=r"(r[0]), "=r"(r[1]), "=r"(r[2]), "=r"(r[3]) : "r"(addr));
}
__device__ __forceinline__ void ldsm2(uint32_t* r, uint32_t addr) {
    asm volatile("ldmatrix.sync.aligned.m8n8.x2.shared.b16 {%0,%1}, [%2];"
                 : "=r"(r[0]), "=r"(r[1]) : "r"(addr));
}
__device__ __forceinline__ void mma_bf16(float* c, const uint32_t* a, const uint32_t* b) {
    asm volatile("mma.sync.aligned.m16n8k16.row.col.f32.bf16.bf16.f32 "
                 "{%0,%1,%2,%3}, {%4,%5,%6,%7}, {%8,%9}, {%0,%1,%2,%3};"
                 : "+f"(c[0]), "+f"(c[1]), "+f"(c[2]), "+f"(c[3])
                 : "r"(a[0]), "r"(a[1]), "r"(a[2]), "r"(a[3]), "r"(b[0]), "r"(b[1]));
}
__device__ __forceinline__ void split2(float v0, float v1, uint32_t& hi, uint32_t& lo) {
    __nv_bfloat162 hp = __floats2bfloat162_rn(v0, v1);
    float h0 = __bfloat162float(__low2bfloat16(hp));
    float h1 = __bfloat162float(__high2bfloat16(hp));
    __nv_bfloat162 lp = __floats2bfloat162_rn(v0 - h0, v1 - h1);
    hi = *reinterpret_cast<uint32_t*>(&hp);
    lo = *reinterpret_cast<uint32_t*>(&lp);
}
__device__ __forceinline__ int edge_at(const void* p, int e) {
    return g_is64 ? (int)((const long long*)p)[e] : ((const int*)p)[e];
}
// gather 4 halfs (8 bytes) -> float4
__device__ __forceinline__ float4 gather_h4(const __half* base, int node, int lane) {
    uint2 raw = *(const uint2*)(base + (size_t)node * IN_F + lane * 4);
    __half2 h0 = *reinterpret_cast<__half2*>(&raw.x);
    __half2 h1 = *reinterpret_cast<__half2*>(&raw.y);
    float2 f0 = __half22float2(h0), f1 = __half22float2(h1);
    return make_float4(f0.x, f0.y, f1.x, f1.y);
}
__device__ __forceinline__ void store_splitB(uint32_t base_off, uint32_t sw, float v0, float v1) {
    uint32_t hi, lo;
    split2(v0, v1, hi, lo);
    *(uint32_t*)(g_Bpack + base_off + sw)         = hi;
    *(uint32_t*)(g_Bpack + base_off + 16384 + sw) = lo;
}

// ---------------- init (+ dtype detect fused) -----------------------------------
__global__ void k_init(const void* __restrict__ dst) {
    int i = blockIdx.x * blockDim.x + threadIdx.x;
    if (i == 0) {
        const long long* p = (const long long*)dst;
        int ok = 1;
        for (int q = 0; q < 64; q++) {
            long long v = p[q];
            if (v < 0 || v >= N_NODES) { ok = 0; break; }
        }
        g_is64 = ok;
        g_scan_count = 0;
    }
    if (i < N_NODES) g_deg[i] = 0;
    if (i < NEIG * OUT_F) g_hs_small[i] = 0.f;
    if (i < OUT_F) { g_colsum[i] = 0.f; g_colsq[i] = 0.f; }
}

// ---------------- fused: count (4 chains) | prepA | prepB chunks 0-7 -------------
#define CP_COUNT 782                         // ceil(800000/4/256)
#define CP_PREPA 18750                       // 50000*96/256
#define CP_C2 (CP_COUNT + CP_PREPA)          // 19532
#define CP_TOTAL (CP_C2 + 128)               // + prepB chunks 0-7
__global__ __launch_bounds__(256) void k_cntprep(const void* __restrict__ e_dst,
                                                 const float* __restrict__ feature,
                                                 const float* __restrict__ evecs,
                                                 const float* __restrict__ lin_w) {
    int b = blockIdx.x, t = threadIdx.x;
    if (b < CP_COUNT) {
        int e = (b * 256 + t) * 4;
        if (e >= N_EDGES) return;
        int d0 = edge_at(e_dst, e);
        int d1 = edge_at(e_dst, e + 1);
        int d2 = edge_at(e_dst, e + 2);
        int d3 = edge_at(e_dst, e + 3);
        atomicAdd(&g_deg[d0], 1);
        atomicAdd(&g_deg[d1], 1);
        atomicAdd(&g_deg[d2], 1);
        atomicAdd(&g_deg[d3], 1);
    } else if (b < CP_C2) {
        int idx = (b - CP_COUNT) * 256 + t;   // float2 slots: 50000*96 exactly
        int n = idx / 96, s = idx - n * 96;
        float2 v; int chunk, kp;
        if (s < 64) {
            v = *(const float2*)(feature + (size_t)n * IN_F + s * 2);
            chunk = s >> 5;
            kp = s & 31;
            __half2 h = __floats2half2_rn(v.x, v.y);
            *(__half2*)(g_Xh[0] + (size_t)n * IN_F + s * 2) = h;
        } else {
            int e = s - 64;
            v = *(const float2*)(evecs + (size_t)n * NEIG + e * 2);
            chunk = 8;
            kp = e;
        }
        uint32_t hi, lo;
        split2(v.x, v.y, hi, lo);
        uint8_t* base = g_Apack + ((size_t)(n >> 7) * N_CHUNKS + chunk) * 32768;
        uint32_t sw = SW128((uint32_t)((n & 127) * 128 + kp * 4));
        *(uint32_t*)(base + sw)         = hi;
        *(uint32_t*)(base + 16384 + sw) = lo;
    } else {
        // prepB chunks 0-7: weight transpose + bf16 split (independent of CSR)
        int idx = (b - CP_C2) * 256 + t;      // < 32768
        int chunk = idx >> 12;
        int rem = idx & 4095;
        int n = rem >> 5, kp = rem & 31;
        int k = chunk * 64 + kp * 2;
        float v0 = lin_w[(size_t)k * OUT_F + n];
        float v1 = lin_w[(size_t)(k + 1) * OUT_F + n];
        store_splitB((uint32_t)chunk * 32768u, SW128((uint32_t)(n * 128 + kp * 4)), v0, v1);
    }
}

// ---------------- single-pass scan (decoupled last-block) + dsqrt ----------------
__global__ void k_scan12() {
    __shared__ int sm[256];
    __shared__ int amLast;
    int t = threadIdx.x, i = blockIdx.x * 256 + t;
    int v = (i < N_NODES) ? g_deg[i] : 0;
    if (i < N_NODES) g_dsqrt[i] = rsqrtf(fmaxf((float)v, 1.f));
    sm[t] = v;
    __syncthreads();
    for (int off = 1; off < 256; off <<= 1) {
        int tmp = (t >= off) ? sm[t - off] : 0;
        __syncthreads();
        sm[t] += tmp;
        __syncthreads();
    }
    if (i < N_NODES) g_rowstart[i] = sm[t] - v;      // per-block partial exclusive
    if (t == 255) g_blocksum[blockIdx.x] = sm[255];
    __threadfence();
    if (t == 0) {
        int c = atomicAdd(&g_scan_count, 1);
        amLast = (c == (int)gridDim.x - 1);
    }
    __syncthreads();
    if (amLast) {
        int nb = (int)gridDim.x;                     // 196
        int v2 = (t < nb) ? g_blocksum[t] : 0;
        sm[t] = v2;
        __syncthreads();
        for (int off = 1; off < 256; off <<= 1) {
            int tmp = (t >= off) ? sm[t - off] : 0;
            __syncthreads();
            sm[t] += tmp;
            __syncthreads();
        }
        g_blockoff[t] = sm[t] - v2;
        if (t == 255) g_rowstart[N_NODES] = sm[255];
    }
}
__global__ void k_scan3() {
    int i = blockIdx.x * blockDim.x + threadIdx.x;
    if (i < N_NODES) {
        int r = g_rowstart[i] + g_blockoff[blockIdx.x];
        g_rowstart[i] = r;
        g_cursor[i] = r;
    }
}

// ---------------- fused: hsacc | eigen MLP ---------------------------------------
#define EH_HSACC 196
__global__ __launch_bounds__(256) void k_eighs(
    const float* __restrict__ evecs, const float* __restrict__ feat,
    const float* __restrict__ evals,
    const float* __restrict__ ew0, const float* __restrict__ eb0,
    const float* __restrict__ ew1, const float* __restrict__ eb1,
    const float* __restrict__ ew2, const float* __restrict__ eb2) {
    int b = blockIdx.x, t = threadIdx.x;
    if (b < EH_HSACC) {
        // ---- hsacc: hs_small = evecs^T @ feature ----
        __shared__ float sev[8][64];
        int f = t & 127;
        int ebase = (t >> 7) * 32;
        float acc[32];
        #pragma unroll
        for (int u = 0; u < 32; u++) acc[u] = 0.f;
        int r0 = b * 256;
        for (int rt = 0; rt < 256; rt += 8) {
            #pragma unroll
            for (int q = 0; q < 2; q++) {
                int idx = q * 256 + t;
                int rr = idx >> 6, ee = idx & 63;
                int grow = r0 + rt + rr;
                sev[rr][ee] = (grow < N_NODES) ? evecs[(size_t)grow * NEIG + ee] : 0.f;
            }
            __syncthreads();
            #pragma unroll
            for (int rr = 0; rr < 8; rr++) {
                int grow = r0 + rt + rr;
                float ftv = (grow < N_NODES) ? feat[(size_t)grow * IN_F + f] : 0.f;
                #pragma unroll
                for (int u4 = 0; u4 < 8; u4++) {
                    float4 ev = *(const float4*)&sev[rr][ebase + u4 * 4];
                    acc[u4*4+0] = fmaf(ev.x, ftv, acc[u4*4+0]);
                    acc[u4*4+1] = fmaf(ev.y, ftv, acc[u4*4+1]);
                    acc[u4*4+2] = fmaf(ev.z, ftv, acc[u4*4+2]);
                    acc[u4*4+3] = fmaf(ev.w, ftv, acc[u4*4+3]);
                }
            }
            __syncthreads();
        }
        #pragma unroll
        for (int u = 0; u < 32; u++)
            atomicAdd(&g_hs_small[(ebase + u) * OUT_F + f], acc[u]);
    } else {
        // ---- eigen MLP -> g_ef[i] (threads 0..127 active) ----
        __shared__ float z0s[HDIM];
        __shared__ float sp[HDIM];
        int i = b - EH_HSACC;
        if (t < HDIM) z0s[t] = fmaxf(fmaf(evals[i], ew0[t], eb0[t]), 0.f);
        __syncthreads();
        if (t < HDIM) {
            float sA = eb1[t], sB = 0.f;
            #pragma unroll 8
            for (int k = 0; k < HDIM; k += 2) {
                sA = fmaf(z0s[k],     ew1[k * HDIM + t],       sA);
                sB = fmaf(z0s[k + 1], ew1[(k + 1) * HDIM + t], sB);
            }
            sp[t] = fmaxf(sA + sB, 0.f) * ew2[t];
        }
        __syncthreads();
        for (int off = 64; off > 0; off >>= 1) {
            if (t < off) sp[t] += sp[t + off];
            __syncthreads();
        }
        if (t == 0) g_ef[i] = sp[0] + eb2[0];
    }
}

// ---------------- fused: place (4 chains) | prepB chunk 8 ------------------------
#define PL_COUNT 782
__global__ __launch_bounds__(256) void k_place(const void* __restrict__ src,
                                               const void* __restrict__ dst,
                                               const float* __restrict__ lin_w) {
    int b = blockIdx.x, t = threadIdx.x;
    if (b < PL_COUNT) {
        int e = (b * 256 + t) * 4;
        if (e >= N_EDGES) return;
        int d0 = edge_at(dst, e);
        int d1 = edge_at(dst, e + 1);
        int d2 = edge_at(dst, e + 2);
        int d3 = edge_at(dst, e + 3);
        int s0 = edge_at(src, e);
        int s1 = edge_at(src, e + 1);
        int s2 = edge_at(src, e + 2);
        int s3 = edge_at(src, e + 3);
        int p0 = atomicAdd(&g_cursor[d0], 1);
        int p1 = atomicAdd(&g_cursor[d1], 1);
        int p2 = atomicAdd(&g_cursor[d2], 1);
        int p3 = atomicAdd(&g_cursor[d3], 1);
        g_csrsrc[p0] = s0;
        g_csrsrc[p1] = s1;
        g_csrsrc[p2] = s2;
        g_csrsrc[p3] = s3;
    } else {
        // prepB chunk 8 (needs g_ef / g_hs_small from k_eighs, which runs before)
        int idx = (b - PL_COUNT) * 256 + t;          // < 4096
        int n = idx >> 5, ep = idx & 31;
        int e0 = ep * 2, e1 = e0 + 1;
        float s0 = 0.f, s1 = 0.f;
        #pragma unroll 4
        for (int f = 0; f < 128; f++) {
            float w = lin_w[(size_t)(512 + f) * OUT_F + n];
            s0 = fmaf(g_hs_small[e0 * OUT_F + f], w, s0);
            s1 = fmaf(g_hs_small[e1 * OUT_F + f], w, s1);
        }
        s0 *= g_ef[e0];
        s1 *= g_ef[e1];
        store_splitB(8u * 32768u, SW128((uint32_t)(n * 128 + ep * 4)), s0, s1);
    }
}

// ---------------- Chebyshev step: fp16 gather (4-edge unroll), fp32 self-terms ---
__global__ void k_cheb(const float* __restrict__ lambda_max,
                       const float* __restrict__ feature,
                       int prevh,                 // fp16 gather source index
                       int prevsel, int prev2sel, // fp32 self-term sources (-1 = feature)
                       int outcol, int first,
                       int chunk_base, int writeXt, int outh) {
    int gwarp = (blockIdx.x * blockDim.x + threadIdx.x) >> 5;
    if (gwarp >= N_NODES) return;
    int lane = threadIdx.x & 31;
    const __half* hx = g_Xh[prevh];
    const float* prev;  size_t ps;
    if (prevsel < 0) { prev = feature; ps = IN_F; }
    else             { prev = g_Xt + prevsel; ps = XT_COLS; }
    int beg = g_rowstart[gwarp], end = g_rowstart[gwarp + 1];
    float4 acc = {0.f, 0.f, 0.f, 0.f};
    int j = beg;
    for (; j + 3 < end; j += 4) {
        int s0 = g_csrsrc[j],     s1 = g_csrsrc[j + 1];
        int s2 = g_csrsrc[j + 2], s3 = g_csrsrc[j + 3];
        float d0 = g_dsqrt[s0], d1 = g_dsqrt[s1];
        float d2 = g_dsqrt[s2], d3 = g_dsqrt[s3];
        float4 v0 = gather_h4(hx, s0, lane);
        float4 v1 = gather_h4(hx, s1, lane);
        float4 v2 = gather_h4(hx, s2, lane);
        float4 v3 = gather_h4(hx, s3, lane);
        acc.x = fmaf(v0.x, d0, acc.x); acc.y = fmaf(v0.y, d0, acc.y);
        acc.z = fmaf(v0.z, d0, acc.z); acc.w = fmaf(v0.w, d0, acc.w);
        acc.x = fmaf(v1.x, d1, acc.x); acc.y = fmaf(v1.y, d1, acc.y);
        acc.z = fmaf(v1.z, d1, acc.z); acc.w = fmaf(v1.w, d1, acc.w);
        acc.x = fmaf(v2.x, d2, acc.x); acc.y = fmaf(v2.y, d2, acc.y);
        acc.z = fmaf(v2.z, d2, acc.z); acc.w = fmaf(v2.w, d2, acc.w);
        acc.x = fmaf(v3.x, d3, acc.x); acc.y = fmaf(v3.y, d3, acc.y);
        acc.z = fmaf(v3.z, d3, acc.z); acc.w = fmaf(v3.w, d3, acc.w);
    }
    for (; j < end; j++) {
        int s0 = g_csrsrc[j];
        float d0 = g_dsqrt[s0];
        float4 v0 = gather_h4(hx, s0, lane);
        acc.x = fmaf(v0.x, d0, acc.x); acc.y = fmaf(v0.y, d0, acc.y);
        acc.z = fmaf(v0.z, d0, acc.z); acc.w = fmaf(v0.w, d0, acc.w);
    }
    float rn = 2.f / lambda_max[0];
    float dn = g_dsqrt[gwarp];
    float alpha = (first ? -rn : -2.f * rn) * dn;
    float beta  = first ? (rn - 1.f) : 2.f * (rn - 1.f);
    float4 xp = *(const float4*)(prev + (size_t)gwarp * ps + lane * 4);
    float4 r;
    r.x = alpha * acc.x + beta * xp.x;
    r.y = alpha * acc.y + beta * xp.y;
    r.z = alpha * acc.z + beta * xp.z;
    r.w = alpha * acc.w + beta * xp.w;
    if (!first) {
        const float* p2; size_t p2s;
        if (prev2sel < 0) { p2 = feature; p2s = IN_F; }
        else              { p2 = g_Xt + prev2sel; p2s = XT_COLS; }
        float4 xpp = *(const float4*)(p2 + (size_t)gwarp * p2s + lane * 4);
        r.x -= xpp.x; r.y -= xpp.y; r.z -= xpp.z; r.w -= xpp.w;
    }
    if (writeXt)
        *(float4*)(g_Xt + (size_t)gwarp * XT_COLS + outcol + lane * 4) = r;
    if (outh >= 0) {
        __half2 ha = __floats2half2_rn(r.x, r.y);
        __half2 hb = __floats2half2_rn(r.z, r.w);
        uint2 packed;
        packed.x = *reinterpret_cast<uint32_t*>(&ha);
        packed.y = *reinterpret_cast<uint32_t*>(&hb);
        *(uint2*)(g_Xh[outh] + (size_t)gwarp * IN_F + lane * 4) = packed;
    }

    // --- emit bf16 hi/lo into pre-swizzled A panel ---
    int tile = gwarp >> 7, rowr = gwarp & 127;
    int chunk = chunk_base + ((lane & 16) >> 4);
    uint8_t* base = g_Apack + ((size_t)tile * N_CHUNKS + chunk) * 32768;
    uint32_t sw = SW128((uint32_t)(rowr * 128 + (lane & 15) * 8));
    uint32_t hi0, lo0, hi1, lo1;
    split2(r.x, r.y, hi0, lo0);
    split2(r.z, r.w, hi1, lo1);
    *(uint32_t*)(base + sw)             = hi0;
    *(uint32_t*)(base + sw + 4)         = hi1;
    *(uint32_t*)(base + 16384 + sw)     = lo0;
    *(uint32_t*)(base + 16384 + sw + 4) = lo1;
}

// ---------------- HMMA GEMM: cp.async tile copies + mma, fused BN stats ----------
#define A_HI 0
#define A_LO 16384
#define B_HI 32768
#define B_LO 49152
#define SMEM_GEMM 65536
__global__ __launch_bounds__(256, 2) void k_gemm_mma(const float* __restrict__ bias,
                                                     float* __restrict__ C) {
    extern __shared__ __align__(16) char smem[];
    uint32_t sb = smem_u32(smem);
    int tid = threadIdx.x, wid = tid >> 5, lane = tid & 31;
    int rowBase = blockIdx.x * 128;
    int rowW = (wid & 3) * 32;
    int colW = (wid >> 2) * 64;

    float c[2][8][4];
    #pragma unroll
    for (int mt = 0; mt < 2; mt++)
        #pragma unroll
        for (int nt = 0; nt < 8; nt++)
            #pragma unroll
            for (int q = 0; q < 4; q++) c[mt][nt][q] = 0.f;

    uint32_t a_row = (uint32_t)(lane & 15);
    uint32_t a_koff = (lane & 16) ? 16u : 0u;
    uint32_t b_row = (uint32_t)(lane & 7);
    uint32_t b_koff = (lane & 8) ? 16u : 0u;

    for (int ch = 0; ch < N_CHUNKS; ch++) {
        __syncthreads();
        const char* asrc = (const char*)(g_Apack + ((size_t)blockIdx.x * N_CHUNKS + ch) * 32768);
        const char* bsrc = (const char*)(g_Bpack + (size_t)ch * 32768);
        #pragma unroll
        for (int q = 0; q < 8; q++)
            CPASYNC16(sb + (uint32_t)(q * 4096 + tid * 16), asrc + q * 4096 + tid * 16);
        #pragma unroll
        for (int q = 0; q < 8; q++)
            CPASYNC16(sb + (uint32_t)(32768 + q * 4096 + tid * 16), bsrc + q * 4096 + tid * 16);
        CPASYNC_COMMIT();
        CPASYNC_WAIT0();
        __syncthreads();

        #pragma unroll
        for (int ks = 0; ks < 4; ks++) {
            uint32_t kb = (uint32_t)ks * 32;
            uint32_t ah[2][4], al[2][4];
            #pragma unroll
            for (int mt = 0; mt < 2; mt++) {
                uint32_t off = SW128((uint32_t)(rowW + mt * 16 + a_row) * 128 + kb + a_koff);
                ldsm4(ah[mt], sb + A_HI + off);
                ldsm4(al[mt], sb + A_LO + off);
            }
            #pragma unroll
            for (int nt = 0; nt < 8; nt++) {
                uint32_t boff = SW128((uint32_t)(colW + nt * 8 + b_row) * 128 + kb + b_koff);
                uint32_t bh[2], bl[2];
                ldsm2(bh, sb + B_HI + boff);
                ldsm2(bl, sb + B_LO + boff);
                #pragma unroll
                for (int mt = 0; mt < 2; mt++) {
                    mma_bf16(c[mt][nt], ah[mt], bh);
                    mma_bf16(c[mt][nt], ah[mt], bl);
                    mma_bf16(c[mt][nt], al[mt], bh);
                }
            }
        }
    }

    // --- epilogue: bias add, store, fused BN column sums ---
    int lane4 = lane & 3, lanerow = lane >> 2;
    float ps[8][2], pq[8][2];
    #pragma unroll
    for (int nt = 0; nt < 8; nt++) { ps[nt][0] = ps[nt][1] = pq[nt][0] = pq[nt][1] = 0.f; }

    #pragma unroll
    for (int mt = 0; mt < 2; mt++) {
        #pragma unroll
        for (int half = 0; half < 2; half++) {
            int grow = rowBase + rowW + mt * 16 + lanerow + half * 8;
            bool valid = grow < N_NODES;
            #pragma unroll
            for (int nt = 0; nt < 8; nt++) {
                int col = colW + nt * 8 + lane4 * 2;
                float v0 = 0.f, v1 = 0.f;
                if (valid) {
                    v0 = c[mt][nt][half * 2 + 0] + __ldg(bias + col);
                    v1 = c[mt][nt][half * 2 + 1] + __ldg(bias + col + 1);
                    float2 w = {v0, v1};
                    *(float2*)(C + (size_t)grow * OUT_F + col) = w;
                }
                ps[nt][0] += v0; ps[nt][1] += v1;
                pq[nt][0] += v0 * v0; pq[nt][1] += v1 * v1;
            }
        }
    }
    #pragma unroll
    for (int nt = 0; nt < 8; nt++) {
        #pragma unroll
        for (int j = 0; j < 2; j++) {
            float s = ps[nt][j], q = pq[nt][j];
            #pragma unroll
            for (int m = 4; m < 32; m <<= 1) {
                s += __shfl_xor_sync(0xffffffffu, s, m);
                q += __shfl_xor_sync(0xffffffffu, q, m);
            }
            if (lanerow == 0) {
                int col = colW + nt * 8 + lane4 * 2 + j;
                atomicAdd(&g_colsum[col], s);
                atomicAdd(&g_colsq[col], q);
            }
        }
    }
}

// ---------------- batch-norm normalize -------------------------------------------
__global__ void k_bnnorm(float* __restrict__ out, const float* __restrict__ gamma,
                         const float* __restrict__ beta) {
    int idx = blockIdx.x * blockDim.x + threadIdx.x;   // float4 index
    if (idx >= N_NODES * 32) return;
    int c4 = idx & 31;
    float4 v = ((float4*)out)[idx];
    float invN = 1.f / (float)N_NODES;
    float r[4];
    float* pv = &v.x;
    #pragma unroll
    for (int u = 0; u < 4; u++) {
        int c = c4 * 4 + u;
        float mu = g_colsum[c] * invN;
        float var = g_colsq[c] * invN - mu * mu;
        float rs = rsqrtf(var + 1e-5f);
        r[u] = fmaxf((pv[u] - mu) * rs * gamma[c] + beta[c], 0.f);
    }
    v.x = r[0]; v.y = r[1]; v.z = r[2]; v.w = r[3];
    ((float4*)out)[idx] = v;
}

// ---------------- launch ----------------------------------------------------------
extern "C" void kernel_launch(void* const* d_in, const int* in_sizes, int n_in,
                              void* d_out, int out_size) {
    const float* feature    = (const float*)d_in[0];
    const float* lin_w      = (const float*)d_in[1];
    const float* lin_b      = (const float*)d_in[2];
    const float* ew0        = (const float*)d_in[3];
    const float* eb0        = (const float*)d_in[4];
    const float* ew1        = (const float*)d_in[5];
    const float* eb1        = (const float*)d_in[6];
    const float* ew2        = (const float*)d_in[7];
    const float* eb2        = (const float*)d_in[8];
    const float* bn_gamma   = (const float*)d_in[9];
    const float* bn_beta    = (const float*)d_in[10];
    const float* lambda_max = (const float*)d_in[11];
    const float* evecs      = (const float*)d_in[12];
    const float* evals      = (const float*)d_in[13];
    const void*  e_src      = (const void*)d_in[14];
    const void*  e_dst      = (const void*)d_in[15];
    float* out = (float*)d_out;

    const int TB = 256;
    int gN    = (N_NODES + TB - 1) / TB;             // 196
    int gF4   = (N_NODES * 32 + TB - 1) / TB;        // 6250
    int gWarp = 6250;                                // warp per node

    cudaFuncSetAttribute(k_gemm_mma, cudaFuncAttributeMaxDynamicSharedMemorySize, SMEM_GEMM);

    k_init<<<gN, TB>>>(e_dst);
    k_cntprep<<<CP_TOTAL, TB>>>(e_dst, feature, evecs, lin_w);  // count | prepA | prepB0-7
    k_scan12<<<gN, TB>>>();
    k_scan3<<<gN, TB>>>();
    k_eighs<<<EH_HSACC + NEIG, TB>>>(evecs, feature, evals,
                                     ew0, eb0, ew1, eb1, ew2, eb2);  // hsacc | eig
    k_place<<<PL_COUNT + 16, TB>>>(e_src, e_dst, lin_w);             // place | prepB8

    // cheb: fp16 gather source, fp32 self-terms, fp16 output copy for next level
    k_cheb<<<gWarp, TB>>>(lambda_max, feature, 0,  -1,  -1,   0, 1, 2, 1, 1);  // X1
    k_cheb<<<gWarp, TB>>>(lambda_max, feature, 1,   0,  -1, 128, 0, 4, 1, 2);  // X2
    k_cheb<<<gWarp, TB>>>(lambda_max, feature, 2, 128,   0, 256, 0, 6, 0, -1); // X3

    k_gemm_mma<<<N_TILES, TB, SMEM_GEMM>>>(lin_b, out);

    k_bnnorm<<<gF4, TB>>>(out, bn_gamma, bn_beta);
}